// round 2
// baseline (speedup 1.0000x reference)
#include <cuda_runtime.h>
#include <cstdint>

typedef unsigned long long u64;

// ---------------- problem constants ----------------
#define TSEQ 16384
#define HID  128
#define GROWS 512   // 4*HID

// ---------------- scratch (device globals; no allocation) ----------------
__device__ float g_pre[(size_t)TSEQ * GROWS];  // gate preactivations (input part), reused for both layers
__device__ float g_h1[(size_t)TSEQ * HID];     // layer-1 hidden states
__device__ float g_h2[(size_t)TSEQ * HID];     // layer-2 hidden states

// ---------------- small helpers ----------------
__device__ __forceinline__ uint32_t smem_u32(const void* p) {
    return (uint32_t)__cvta_generic_to_shared(p);
}

__device__ __forceinline__ u64 ffma2(u64 a, u64 b, u64 c) {
    u64 d;
    asm("fma.rn.f32x2 %0, %1, %2, %3;" : "=l"(d) : "l"(a), "l"(b), "l"(c));
    return d;
}
__device__ __forceinline__ u64 fadd2(u64 a, u64 b) {
    u64 d;
    asm("add.rn.f32x2 %0, %1, %2;" : "=l"(d) : "l"(a), "l"(b));
    return d;
}
__device__ __forceinline__ float2 unpack2(u64 a) {
    float2 r;
    asm("mov.b64 {%0, %1}, %2;" : "=f"(r.x), "=f"(r.y) : "l"(a));
    return r;
}

// accurate-enough fast activations (MUFU ex2 path, ~1e-6 rel err; robust at +-inf)
__device__ __forceinline__ float fast_sigmoid(float x) {
    return __fdividef(1.f, 1.f + __expf(-x));
}
__device__ __forceinline__ float fast_tanh(float x) {
    return 1.f - __fdividef(2.f, __expf(2.f * x) + 1.f);
}

__device__ __forceinline__ void mbar_wait_cluster(uint32_t addr, unsigned parity) {
    asm volatile(
        "{\n\t"
        ".reg .pred P1;\n\t"
        "WAIT_%=:\n\t"
        "mbarrier.try_wait.parity.acquire.cluster.shared::cta.b64 P1, [%0], %1, 0x989680;\n\t"
        "@P1 bra DONE_%=;\n\t"
        "bra WAIT_%=;\n\t"
        "DONE_%=:\n\t"
        "}"
        :: "r"(addr), "r"(parity) : "memory");
}

// ============================================================================
// Sequential LSTM scan: 2-CTA cluster, W_hh entirely in registers.
// CTA rank r owns hidden indices j in [64r, 64r+64) -> 256 rows of W_hh:
//   thread tid: gate = tid>>6 (i,f,g,o), jj = tid&63, row = gate*128 + 64r + jj.
// Per step: matvec (f32x2 FFMA, weights in regs, h broadcast from SMEM),
// gate exchange through SMEM, owners (tid<64) update c/h, write h-slice
// locally + to peer via DSMEM, mbarrier handoff (double-buffered).
// ============================================================================
__global__ void __cluster_dims__(2, 1, 1) __launch_bounds__(256, 1)
lstm_scan_kernel(const float* __restrict__ W_hh, int layer)
{
    __shared__ __align__(16) float h_sm[2][HID];
    __shared__ float act_sm[256];
    __shared__ __align__(8) u64 mbar[2];

    const float* __restrict__ pre = g_pre;
    float* __restrict__ hout = layer ? g_h2 : g_h1;

    const int tid = threadIdx.x;
    unsigned rank;
    asm("mov.u32 %0, %%cluster_ctarank;" : "=r"(rank));
    const unsigned peer = rank ^ 1u;

    const int gate = tid >> 6;            // 0..3 = i,f,g,o
    const int jj   = tid & 63;
    const int j    = (int)rank * 64 + jj; // hidden index
    const int grow = gate * HID + j;      // global gate row [0,512)

    // ---- load this thread's W_hh row (128 floats) into regs as 64 f32x2 pairs
    u64 w[64];
    const ulonglong2* wsrc = reinterpret_cast<const ulonglong2*>(W_hh + (size_t)grow * HID);
#pragma unroll
    for (int k = 0; k < 32; k++) {
        ulonglong2 v = wsrc[k];
        w[2 * k]     = v.x;
        w[2 * k + 1] = v.y;
    }

    // ---- init state / barriers
    if (tid < HID) { h_sm[0][tid] = 0.f; h_sm[1][tid] = 0.f; }
    const uint32_t mbar_addr = smem_u32(&mbar[0]);
    if (tid == 0) {
        asm volatile("mbarrier.init.shared.b64 [%0], %1;" :: "r"(mbar_addr),      "r"(64u));
        asm volatile("mbarrier.init.shared.b64 [%0], %1;" :: "r"(mbar_addr + 8u), "r"(64u));
        asm volatile("fence.mbarrier_init.release.cluster;" ::: "memory");
    }
    __syncthreads();
    asm volatile("barrier.cluster.arrive.aligned;" ::: "memory");
    asm volatile("barrier.cluster.wait.aligned;"   ::: "memory");

    const uint32_t h_base = smem_u32(&h_sm[0][0]);
    uint32_t peer_h_base, peer_mbar;
    asm("mapa.shared::cluster.u32 %0, %1, %2;" : "=r"(peer_h_base) : "r"(h_base),    "r"(peer));
    asm("mapa.shared::cluster.u32 %0, %1, %2;" : "=r"(peer_mbar)   : "r"(mbar_addr), "r"(peer));

    float c = 0.f;                     // cell state (owners tid<64)
    float pre_cur = pre[grow];         // software-pipelined gate-input load
    unsigned phase0 = 0, phase1 = 0;
    int cur = 0;

    for (int s = 0; s < TSEQ; s++) {
        // prefetch next step's input preactivation (hidden under full step)
        float pre_nxt = (s + 1 < TSEQ) ? pre[(size_t)(s + 1) * GROWS + grow] : 0.f;

        // ---- matvec: dot(W_hh[row,:], h) with packed f32x2 FMAs
        u64 a0 = 0ull, a1 = 0ull, a2 = 0ull, a3 = 0ull;
        const ulonglong2* hv2 = reinterpret_cast<const ulonglong2*>(&h_sm[cur][0]);
#pragma unroll
        for (int k = 0; k < 32; k++) {
            ulonglong2 hp = hv2[k];   // LDS.128 broadcast
            if (k & 1) {
                a2 = ffma2(w[2 * k],     hp.x, a2);
                a3 = ffma2(w[2 * k + 1], hp.y, a3);
            } else {
                a0 = ffma2(w[2 * k],     hp.x, a0);
                a1 = ffma2(w[2 * k + 1], hp.y, a1);
            }
        }
        float2 ar = unpack2(fadd2(fadd2(a0, a1), fadd2(a2, a3)));
        float gval = ar.x + ar.y + pre_cur;

        float av = (gate == 2) ? fast_tanh(gval) : fast_sigmoid(gval);
        act_sm[tid] = av;
        __syncthreads();

        const int nxt = cur ^ 1;
        if (tid < 64) {
            float iv = act_sm[tid];
            float fv = act_sm[64 + tid];
            float gv = act_sm[128 + tid];
            float ov = act_sm[192 + tid];
            c = fv * c + iv * gv;
            float hv = ov * fast_tanh(c);

            h_sm[nxt][j] = hv;  // local slice
            // remote slice -> peer CTA's h buffer
            uint32_t raddr = peer_h_base + (uint32_t)(nxt * HID + j) * 4u;
            asm volatile("st.shared::cluster.f32 [%0], %1;" :: "r"(raddr), "f"(hv) : "memory");
            // release-arrive on peer's barrier (orders the store above)
            uint32_t rbar = peer_mbar + (uint32_t)nxt * 8u;
            asm volatile("mbarrier.arrive.release.cluster.shared::cluster.b64 _, [%0];"
                         :: "r"(rbar) : "memory");
            // stream h out for the next layer / FC
            hout[(size_t)s * HID + j] = hv;
        }
        __syncthreads();  // local slice of h_sm[nxt] visible intra-CTA

        // wait for the peer's 64 arrivals (peer slice of h_sm[nxt] now visible)
        unsigned ph = nxt ? phase1 : phase0;
        mbar_wait_cluster(mbar_addr + (uint32_t)nxt * 8u, ph);
        if (nxt) phase1 ^= 1u; else phase0 ^= 1u;

        pre_cur = pre_nxt;
        cur = nxt;
    }

    asm volatile("barrier.cluster.arrive.aligned;" ::: "memory");
    asm volatile("barrier.cluster.wait.aligned;"   ::: "memory");
}

// ============================================================================
// Input projection: g_pre[t, r] = (ba[r] + bb[r]) + sum_k A[t,k] * W[r,k]
// A = external x (useH1=0, K=50) or g_h1 (useH1=1, K=128). R = 512 fixed.
// Block = 512 threads (one per r), BT=8 timesteps per block.
// ============================================================================
template <int K>
__global__ void __launch_bounds__(512)
addmm_kernel(const float* __restrict__ Aext, int useH1,
             const float* __restrict__ W,
             const float* __restrict__ ba, const float* __restrict__ bb)
{
    constexpr int BT = 8;
    const float* __restrict__ A = useH1 ? g_h1 : Aext;
    __shared__ float As[BT * K];

    const int t0 = blockIdx.x * BT;
    for (int idx = threadIdx.x; idx < BT * K; idx += 512)
        As[idx] = A[(size_t)t0 * K + idx];
    __syncthreads();

    const int r = threadIdx.x;
    float bias = ba[r] + bb[r];
    float acc[BT];
#pragma unroll
    for (int i = 0; i < BT; i++) acc[i] = bias;

    const float* wr = W + (size_t)r * K;
#pragma unroll 2
    for (int k = 0; k < K; k++) {
        float wv = __ldg(wr + k);
#pragma unroll
        for (int i = 0; i < BT; i++) acc[i] = fmaf(wv, As[i * K + k], acc[i]);
    }
#pragma unroll
    for (int i = 0; i < BT; i++)
        g_pre[(size_t)(t0 + i) * GROWS + r] = acc[i];
}

// ============================================================================
// Final FC: out[t, o] = fc_b[o] + sum_k g_h2[t,k] * fc_W[o,k]   (OUT = 5)
// ============================================================================
__global__ void __launch_bounds__(256)
fc_kernel(const float* __restrict__ fcW, const float* __restrict__ fcb,
          float* __restrict__ out)
{
    __shared__ float Ws[5 * HID];
    __shared__ float bs[5];
    for (int idx = threadIdx.x; idx < 5 * HID; idx += 256) Ws[idx] = fcW[idx];
    if (threadIdx.x < 5) bs[threadIdx.x] = fcb[threadIdx.x];
    __syncthreads();

    const int t = blockIdx.x * 256 + threadIdx.x;
    float acc[5];
#pragma unroll
    for (int o = 0; o < 5; o++) acc[o] = bs[o];

    const float4* hp = reinterpret_cast<const float4*>(&g_h2[(size_t)t * HID]);
#pragma unroll 4
    for (int k4 = 0; k4 < HID / 4; k4++) {
        float4 h = hp[k4];
#pragma unroll
        for (int o = 0; o < 5; o++) {
            acc[o] = fmaf(h.x, Ws[o * HID + 4 * k4 + 0], acc[o]);
            acc[o] = fmaf(h.y, Ws[o * HID + 4 * k4 + 1], acc[o]);
            acc[o] = fmaf(h.z, Ws[o * HID + 4 * k4 + 2], acc[o]);
            acc[o] = fmaf(h.w, Ws[o * HID + 4 * k4 + 3], acc[o]);
        }
    }
#pragma unroll
    for (int o = 0; o < 5; o++) out[(size_t)t * 5 + o] = acc[o];
}

// ============================================================================
// kernel_launch: pre1 GEMM -> scan L1 -> pre2 GEMM -> scan L2 -> FC
// ============================================================================
extern "C" void kernel_launch(void* const* d_in, const int* in_sizes, int n_in,
                              void* d_out, int out_size)
{
    (void)in_sizes; (void)n_in; (void)out_size;

    const float* x     = (const float*)d_in[0];
    const float* W_ih1 = (const float*)d_in[1];
    const float* W_hh1 = (const float*)d_in[2];
    const float* b_ih1 = (const float*)d_in[3];
    const float* b_hh1 = (const float*)d_in[4];
    const float* W_ih2 = (const float*)d_in[5];
    const float* W_hh2 = (const float*)d_in[6];
    const float* b_ih2 = (const float*)d_in[7];
    const float* b_hh2 = (const float*)d_in[8];
    const float* fc_W  = (const float*)d_in[9];
    const float* fc_b  = (const float*)d_in[10];
    float* out = (float*)d_out;

    // 1) pre1 = x @ W_ih1^T + (b_ih1 + b_hh1)
    addmm_kernel<50><<<TSEQ / 8, 512>>>(x, 0, W_ih1, b_ih1, b_hh1);
    // 2) layer-1 sequential scan (2-CTA cluster)
    lstm_scan_kernel<<<2, 256>>>(W_hh1, 0);
    // 3) pre2 = h1 @ W_ih2^T + (b_ih2 + b_hh2)
    addmm_kernel<128><<<TSEQ / 8, 512>>>(nullptr, 1, W_ih2, b_ih2, b_hh2);
    // 4) layer-2 sequential scan
    lstm_scan_kernel<<<2, 256>>>(W_hh2, 1);
    // 5) out = h2 @ fc_W^T + fc_b
    fc_kernel<<<TSEQ / 256, 256>>>(fc_W, fc_b, out);
}